// round 13
// baseline (speedup 1.0000x reference)
#include <cuda_runtime.h>
#include <cuda_fp16.h>
#include <cstdint>

// PointNetSaModule via mma.sync fp16 (sm_103-safe HMMA), single-term A and W.
// R12: A and W both fp16 (1 MMA per tile); 256 threads / 256 rows per CTA,
// smem ~92KB -> 2 CTAs per SM (launch_bounds(256,2)) for cross-CTA overlap.
// Layers 67->64->64->128 (BN folded), ReLU, max over each 16-row group.

typedef uint32_t u32;
typedef uint64_t u64;

#define NS_SZ  16384
#define HW_SZ  65536
#define OUT_ONE (4 * 16384 * 128)
#define THREADS 256
#define WARPS   8
#define ROWS    256

// u32 offsets in dynamic smem
#define OFF_T0    0
#define OFF_T1    64
#define OFF_T2    128
#define OFF_S0    256
#define OFF_S1    320
#define OFF_S2    384
#define OFF_AH    512                     // 256 rows x 40 u32 (fp16x2 kpairs)
#define OFF_W0    (OFF_AH + ROWS * 40)    // 10752 (64 x 40)
#define OFF_W1    (OFF_W0 + 64 * 40)      // 13312
#define OFF_W2    (OFF_W1 + 64 * 40)      // 15872 (128 x 40)
#define OFF_STAGE (OFF_W2 + 128 * 40)     // 20992 (8 warps x 256 f32)
#define SMEM_U32  (OFF_STAGE + WARPS * 256)   // 23040
#define SMEM_BYTES (SMEM_U32 * 4)             // 92160

// physical slot of logical kpair p (interleave (c, c+4) adjacent within ktile)
__device__ __forceinline__ int POS(int p) {
    int q = p & 7;
    return (p & ~7) + ((q < 4) ? 2 * q : 2 * (q - 4) + 1);
}

__device__ __forceinline__ u32 packh2(float lo, float hi) {   // low half = lo
    __half2 h = __floats2half2_rn(lo, hi);
    return *(u32*)&h;
}
__device__ __forceinline__ void mma_f16(float* d, u32 a0, u32 a1, u32 a2, u32 a3,
                                        u32 b0, u32 b1) {
    asm("mma.sync.aligned.m16n8k16.row.col.f32.f16.f16.f32 "
        "{%0,%1,%2,%3}, {%4,%5,%6,%7}, {%8,%9}, {%0,%1,%2,%3};"
        : "+f"(d[0]), "+f"(d[1]), "+f"(d[2]), "+f"(d[3])
        : "r"(a0), "r"(a1), "r"(a2), "r"(a3), "r"(b0), "r"(b1));
}
__device__ __forceinline__ u32 lo32(u64 v) { return (u32)v; }
__device__ __forceinline__ u32 hi32(u64 v) { return (u32)(v >> 32); }

// Load one ktile's A fragment for the m-tile at rowA (PTX m16n8k16 A map).
__device__ __forceinline__ void load_afrag(u32 ah[4], const u64* AHu,
                                           int rowA, int kt, int c)
{
    u64 v0 = AHu[rowA * 20 + kt * 4 + c];
    u64 v1 = AHu[(rowA + 8) * 20 + kt * 4 + c];
    ah[0] = lo32(v0); ah[2] = hi32(v0);
    ah[1] = lo32(v1); ah[3] = hi32(v1);
}

// bias + ReLU + fp16 writeback of 64 channels into act rows (one m-tile)
__device__ __forceinline__ void epi_store(float d[][4], u64* AHu,
        const float* T, int rowA, int c)
{
    #pragma unroll
    for (int t = 0; t < 4; t++) {
        float2 tA = *(const float2*)(T + 16 * t + 2 * c);
        float2 tB = *(const float2*)(T + 16 * t + 8 + 2 * c);
        {
            u32 hA = packh2(fmaxf(d[2*t][0]   + tA.x, 0.f), fmaxf(d[2*t][1]   + tA.y, 0.f));
            u32 hB = packh2(fmaxf(d[2*t+1][0] + tB.x, 0.f), fmaxf(d[2*t+1][1] + tB.y, 0.f));
            AHu[rowA * 20 + 4 * t + c] = (u64)hA | ((u64)hB << 32);
        }
        {
            u32 hA = packh2(fmaxf(d[2*t][2]   + tA.x, 0.f), fmaxf(d[2*t][3]   + tA.y, 0.f));
            u32 hB = packh2(fmaxf(d[2*t+1][2] + tB.x, 0.f), fmaxf(d[2*t+1][3] + tB.y, 0.f));
            AHu[(rowA + 8) * 20 + 4 * t + c] = (u64)hA | ((u64)hB << 32);
        }
    }
}

// One N=64 layer for a warp's 32 rows (2 m-tiles), in-place act update.
template<int NKT>
__device__ __forceinline__ void layer_n64(u64* AHu, const u64* Wu,
        const float* T, int base, int r, int c)
{
    float d[2][8][4];
    #pragma unroll
    for (int m = 0; m < 2; m++)
        #pragma unroll
        for (int j = 0; j < 8; j++)
            { d[m][j][0]=0.f; d[m][j][1]=0.f; d[m][j][2]=0.f; d[m][j][3]=0.f; }
    #pragma unroll
    for (int kt = 0; kt < NKT; kt++) {
        u32 a0[4], a1[4];
        load_afrag(a0, AHu, base + r,      kt, c);
        load_afrag(a1, AHu, base + 16 + r, kt, c);
        #pragma unroll
        for (int j = 0; j < 8; j++) {
            u64 b = Wu[(8 * j + r) * 20 + kt * 4 + c];
            u32 b0 = lo32(b), b1 = hi32(b);
            mma_f16(d[0][j], a0[0], a0[1], a0[2], a0[3], b0, b1);
            mma_f16(d[1][j], a1[0], a1[1], a1[2], a1[3], b0, b1);
        }
    }
    __syncwarp();
    epi_store(d[0], AHu, T, base + r,      c);
    epi_store(d[1], AHu, T, base + 16 + r, c);
    __syncwarp();
}

__global__ void __launch_bounds__(THREADS, 2)
pointnet_sa_hmma4_kernel(
    const float* __restrict__ xyz, const float* __restrict__ pts,
    const float* __restrict__ xyzs, const int* __restrict__ nbr,
    const float* __restrict__ vmask,
    const float* __restrict__ w0, const float* __restrict__ b0,
    const float* __restrict__ g0, const float* __restrict__ be0,
    const float* __restrict__ m0, const float* __restrict__ v0,
    const float* __restrict__ w1, const float* __restrict__ b1,
    const float* __restrict__ g1, const float* __restrict__ be1,
    const float* __restrict__ m1, const float* __restrict__ v1,
    const float* __restrict__ w2, const float* __restrict__ b2,
    const float* __restrict__ g2, const float* __restrict__ be2,
    const float* __restrict__ m2, const float* __restrict__ v2,
    float* __restrict__ out, int copies)
{
    extern __shared__ u32 smu[];
    float* smf = (float*)smu;
    const int tid = threadIdx.x;

    // ---- BN fold scales + biases ----
    if (tid < 64) {
        float s = g0[tid] * rsqrtf(v0[tid] + 1e-5f);
        smf[OFF_S0 + tid] = s;
        smf[OFF_T0 + tid] = (b0[tid] - m0[tid]) * s + be0[tid];
        float s1 = g1[tid] * rsqrtf(v1[tid] + 1e-5f);
        smf[OFF_S1 + tid] = s1;
        smf[OFF_T1 + tid] = (b1[tid] - m1[tid]) * s1 + be1[tid];
    }
    if (tid < 128) {
        float s = g2[tid] * rsqrtf(v2[tid] + 1e-5f);
        smf[OFF_S2 + tid] = s;
        smf[OFF_T2 + tid] = (b2[tid] - m2[tid]) * s + be2[tid];
    }
    __syncthreads();

    // ---- weight tiles (fp16x2, [n][kpair phys], stride 40 u32) ----
    for (int i = tid; i < 64 * 40; i += THREADS) {
        int n = i / 40, pos = i % 40;
        int q = pos & 7;
        int p = (pos & ~7) + ((q & 1) ? (q >> 1) + 4 : (q >> 1));
        int k0 = 2 * p, k1 = k0 + 1;
        float s = smf[OFF_S0 + n];
        float a = 0.f, b = 0.f;
        if (k0 < 67) { int sr = (k0 < 64) ? k0 + 3 : k0 - 64; a = w0[sr * 64 + n] * s; }
        if (k1 < 67) { int sr = (k1 < 64) ? k1 + 3 : k1 - 64; b = w0[sr * 64 + n] * s; }
        smu[OFF_W0 + i] = packh2(a, b);
    }
    for (int i = tid; i < 64 * 40; i += THREADS) {
        int n = i / 40, pos = i % 40;
        int q = pos & 7;
        int p = (pos & ~7) + ((q & 1) ? (q >> 1) + 4 : (q >> 1));
        int k0 = 2 * p;
        float s = smf[OFF_S1 + n];
        float a = (k0 < 64)     ? w1[k0 * 64 + n] * s       : 0.f;
        float b = (k0 + 1 < 64) ? w1[(k0 + 1) * 64 + n] * s : 0.f;
        smu[OFF_W1 + i] = packh2(a, b);
    }
    for (int i = tid; i < 128 * 40; i += THREADS) {
        int n = i / 40, pos = i % 40;
        int q = pos & 7;
        int p = (pos & ~7) + ((q & 1) ? (q >> 1) + 4 : (q >> 1));
        int k0 = 2 * p;
        float s = smf[OFF_S2 + n];
        float a = (k0 < 64)     ? w2[k0 * 128 + n] * s       : 0.f;
        float b = (k0 + 1 < 64) ? w2[(k0 + 1) * 128 + n] * s : 0.f;
        smu[OFF_W2 + i] = packh2(a, b);
    }

    // ---- gather: thread owns row = tid (256 rows/CTA), fp16 rounding here ----
    {
        const int r = tid;
        const int grp = blockIdx.x * 16 + (r >> 4);
        const int b = grp >> 14, n = grp & (NS_SZ - 1);
        const int e = grp * 16 + (r & 15);
        const int idx = nbr[e];
        const float mk = vmask[e];
        const float4* pp = (const float4*)(pts + (size_t)(b * HW_SZ + idx) * 64);
        u32* AH = smu + OFF_AH + r * 40;
        #pragma unroll
        for (int i = 0; i < 16; i++) {
            float4 v = pp[i];
            AH[POS(2 * i)]     = packh2(v.x * mk, v.y * mk);
            AH[POS(2 * i + 1)] = packh2(v.z * mk, v.w * mk);
        }
        const float* cp = xyzs + (size_t)(b * NS_SZ + n) * 3;
        const float* gx = xyz + (size_t)(b * HW_SZ + idx) * 3;
        AH[32] = packh2(gx[0] * mk - cp[0], gx[1] * mk - cp[1]);   // POS(32)=32
        AH[34] = packh2(gx[2] * mk - cp[2], 0.f);                  // POS(33)=34
        AH[33] = 0;
        #pragma unroll
        for (int z = 35; z < 40; z++) AH[z] = 0;
    }
    __syncthreads();

    const int lane = tid & 31;
    const int warp = tid >> 5;
    const int r = lane >> 2;       // groupID in quad layout
    const int c = lane & 3;        // threadID in group
    const int base = warp * 32;    // this warp's first row

    u64* AHu = (u64*)(smu + OFF_AH);
    const u64* W0u = (const u64*)(smu + OFF_W0);
    const u64* W1u = (const u64*)(smu + OFF_W1);
    const u64* W2u = (const u64*)(smu + OFF_W2);

    // ===== layers 0 and 1 =====
    layer_n64<5>(AHu, W0u, smf + OFF_T0, base, r, c);
    layer_n64<4>(AHu, W1u, smf + OFF_T1, base, r, c);

    // ===== layer 2: K=64, N=128 in two passes; maxpool per 16-row group =====
    float* stage = smf + OFF_STAGE + warp * 256;
    #pragma unroll 1
    for (int p = 0; p < 2; p++) {
        float d[2][8][4];
        #pragma unroll
        for (int m = 0; m < 2; m++)
            #pragma unroll
            for (int j = 0; j < 8; j++)
                { d[m][j][0]=0.f; d[m][j][1]=0.f; d[m][j][2]=0.f; d[m][j][3]=0.f; }
        #pragma unroll
        for (int kt = 0; kt < 4; kt++) {
            u32 a0[4], a1[4];
            load_afrag(a0, AHu, base + r,      kt, c);
            load_afrag(a1, AHu, base + 16 + r, kt, c);
            #pragma unroll
            for (int j = 0; j < 8; j++) {
                u64 b = W2u[(64 * p + 8 * j + r) * 20 + kt * 4 + c];
                u32 b0 = lo32(b), b1 = hi32(b);
                mma_f16(d[0][j], a0[0], a0[1], a0[2], a0[3], b0, b1);
                mma_f16(d[1][j], a1[0], a1[1], a1[2], a1[3], b0, b1);
            }
        }
        #pragma unroll
        for (int m = 0; m < 2; m++) {
            float mx0[8], mx1[8];
            #pragma unroll
            for (int j = 0; j < 8; j++) {
                mx0[j] = fmaxf(d[m][j][0], d[m][j][2]);
                mx1[j] = fmaxf(d[m][j][1], d[m][j][3]);
            }
            #pragma unroll
            for (int off = 4; off <= 16; off <<= 1) {
                #pragma unroll
                for (int j = 0; j < 8; j++) {
                    mx0[j] = fmaxf(mx0[j], __shfl_xor_sync(0xffffffffu, mx0[j], off));
                    mx1[j] = fmaxf(mx1[j], __shfl_xor_sync(0xffffffffu, mx1[j], off));
                }
            }
            if (lane < 4) {
                #pragma unroll
                for (int j = 0; j < 8; j++) {
                    float2 tv = *(const float2*)(smf + OFF_T2 + 64 * p + 8 * j + 2 * c);
                    float2 o;
                    o.x = fmaxf(mx0[j] + tv.x, 0.f);
                    o.y = fmaxf(mx1[j] + tv.y, 0.f);
                    *(float2*)(stage + m * 128 + 64 * p + 8 * j + 2 * c) = o;
                }
            }
        }
    }
    __syncwarp();

    // ---- coalesced output: 2 groups x 128 floats per warp ----
    #pragma unroll
    for (int m = 0; m < 2; m++) {
        float4 o = ((const float4*)(stage + m * 128))[lane];
        const long ofs = (long)(blockIdx.x * 16 + warp * 2 + m) * 128 + 4 * lane;
        *(float4*)(out + ofs) = o;
        if (copies > 1) *(float4*)(out + OUT_ONE + ofs) = o;
    }
}

extern "C" void kernel_launch(void* const* d_in, const int* in_sizes, int n_in,
                              void* d_out, int out_size)
{
    const float* xyz   = (const float*)d_in[0];
    const float* pts   = (const float*)d_in[1];
    const float* xyzs  = (const float*)d_in[2];
    const int*   nbr   = (const int*)  d_in[3];
    const float* vmask = (const float*)d_in[4];
    const float* w0  = (const float*)d_in[5];
    const float* b0  = (const float*)d_in[6];
    const float* g0  = (const float*)d_in[7];
    const float* be0 = (const float*)d_in[8];
    const float* m0  = (const float*)d_in[9];
    const float* v0  = (const float*)d_in[10];
    const float* w1  = (const float*)d_in[11];
    const float* b1  = (const float*)d_in[12];
    const float* g1  = (const float*)d_in[13];
    const float* be1 = (const float*)d_in[14];
    const float* m1  = (const float*)d_in[15];
    const float* v1  = (const float*)d_in[16];
    const float* w2  = (const float*)d_in[17];
    const float* b2  = (const float*)d_in[18];
    const float* g2  = (const float*)d_in[19];
    const float* be2 = (const float*)d_in[20];
    const float* m2  = (const float*)d_in[21];
    const float* v2  = (const float*)d_in[22];

    int copies = (out_size >= 2 * OUT_ONE) ? 2 : 1;

    cudaFuncSetAttribute(pointnet_sa_hmma4_kernel,
                         cudaFuncAttributeMaxDynamicSharedMemorySize, SMEM_BYTES);

    const int blocks = (4 * NS_SZ) / 16;   // 4096 CTAs x 256 rows
    pointnet_sa_hmma4_kernel<<<blocks, THREADS, SMEM_BYTES>>>(
        xyz, pts, xyzs, nbr, vmask,
        w0, b0, g0, be0, m0, v0,
        w1, b1, g1, be1, m1, v1,
        w2, b2, g2, be2, m2, v2,
        (float*)d_out, copies);
}

// round 14
// speedup vs baseline: 2.9829x; 2.9829x over previous
#include <cuda_runtime.h>
#include <cuda_fp16.h>
#include <cstdint>

// PointNetSaModule via mma.sync fp16 (sm_103-safe HMMA), persistent warps.
// R13: 304 CTAs (2/SM); weight/BN setup ONCE per CTA; each warp grid-strides
// over 32768 independent 32-row tasks with no CTA barriers (warp-private rows).
// A and W fp16 single-term; layers 67->64->64->128, ReLU, max per 16-row group.

typedef uint32_t u32;
typedef uint64_t u64;

#define NS_SZ  16384
#define HW_SZ  65536
#define OUT_ONE (4 * 16384 * 128)
#define THREADS 256
#define WARPS   8
#define NTASK   32768          // 1M rows / 32
#define GRID    304            // 2 per SM

// u32 offsets in dynamic smem
#define OFF_T0    0
#define OFF_T1    64
#define OFF_T2    128
#define OFF_S0    256
#define OFF_S1    320
#define OFF_S2    384
#define OFF_AH    512                     // 256 rows x 40 u32 (fp16x2 kpairs)
#define OFF_W0    (OFF_AH + 256 * 40)     // 10752 (64 x 40)
#define OFF_W1    (OFF_W0 + 64 * 40)      // 13312
#define OFF_W2    (OFF_W1 + 64 * 40)      // 15872 (128 x 40)
#define OFF_STAGE (OFF_W2 + 128 * 40)     // 20992 (8 warps x 256 f32)
#define SMEM_U32  (OFF_STAGE + WARPS * 256)   // 23040
#define SMEM_BYTES (SMEM_U32 * 4)             // 92160

// physical slot of logical kpair p (interleave (c, c+4) adjacent within ktile)
__device__ __forceinline__ int POS(int p) {
    int q = p & 7;
    return (p & ~7) + ((q < 4) ? 2 * q : 2 * (q - 4) + 1);
}

__device__ __forceinline__ u32 packh2(float lo, float hi) {   // low half = lo
    __half2 h = __floats2half2_rn(lo, hi);
    return *(u32*)&h;
}
__device__ __forceinline__ void mma_f16(float* d, u32 a0, u32 a1, u32 a2, u32 a3,
                                        u32 b0, u32 b1) {
    asm("mma.sync.aligned.m16n8k16.row.col.f32.f16.f16.f32 "
        "{%0,%1,%2,%3}, {%4,%5,%6,%7}, {%8,%9}, {%0,%1,%2,%3};"
        : "+f"(d[0]), "+f"(d[1]), "+f"(d[2]), "+f"(d[3])
        : "r"(a0), "r"(a1), "r"(a2), "r"(a3), "r"(b0), "r"(b1));
}
__device__ __forceinline__ u32 lo32(u64 v) { return (u32)v; }
__device__ __forceinline__ u32 hi32(u64 v) { return (u32)(v >> 32); }

__device__ __forceinline__ void load_afrag(u32 ah[4], const u64* AHu,
                                           int rowA, int kt, int c)
{
    u64 v0 = AHu[rowA * 20 + kt * 4 + c];
    u64 v1 = AHu[(rowA + 8) * 20 + kt * 4 + c];
    ah[0] = lo32(v0); ah[2] = hi32(v0);
    ah[1] = lo32(v1); ah[3] = hi32(v1);
}

__device__ __forceinline__ void epi_store(float d[][4], u64* AHu,
        const float* T, int rowA, int c)
{
    #pragma unroll
    for (int t = 0; t < 4; t++) {
        float2 tA = *(const float2*)(T + 16 * t + 2 * c);
        float2 tB = *(const float2*)(T + 16 * t + 8 + 2 * c);
        {
            u32 hA = packh2(fmaxf(d[2*t][0]   + tA.x, 0.f), fmaxf(d[2*t][1]   + tA.y, 0.f));
            u32 hB = packh2(fmaxf(d[2*t+1][0] + tB.x, 0.f), fmaxf(d[2*t+1][1] + tB.y, 0.f));
            AHu[rowA * 20 + 4 * t + c] = (u64)hA | ((u64)hB << 32);
        }
        {
            u32 hA = packh2(fmaxf(d[2*t][2]   + tA.x, 0.f), fmaxf(d[2*t][3]   + tA.y, 0.f));
            u32 hB = packh2(fmaxf(d[2*t+1][2] + tB.x, 0.f), fmaxf(d[2*t+1][3] + tB.y, 0.f));
            AHu[(rowA + 8) * 20 + 4 * t + c] = (u64)hA | ((u64)hB << 32);
        }
    }
}

template<int NKT>
__device__ __forceinline__ void layer_n64(u64* AHu, const u64* Wu,
        const float* T, int base, int r, int c)
{
    float d[2][8][4];
    #pragma unroll
    for (int m = 0; m < 2; m++)
        #pragma unroll
        for (int j = 0; j < 8; j++)
            { d[m][j][0]=0.f; d[m][j][1]=0.f; d[m][j][2]=0.f; d[m][j][3]=0.f; }
    #pragma unroll
    for (int kt = 0; kt < NKT; kt++) {
        u32 a0[4], a1[4];
        load_afrag(a0, AHu, base + r,      kt, c);
        load_afrag(a1, AHu, base + 16 + r, kt, c);
        #pragma unroll
        for (int j = 0; j < 8; j++) {
            u64 b = Wu[(8 * j + r) * 20 + kt * 4 + c];
            u32 b0 = lo32(b), b1 = hi32(b);
            mma_f16(d[0][j], a0[0], a0[1], a0[2], a0[3], b0, b1);
            mma_f16(d[1][j], a1[0], a1[1], a1[2], a1[3], b0, b1);
        }
    }
    __syncwarp();
    epi_store(d[0], AHu, T, base + r,      c);
    epi_store(d[1], AHu, T, base + 16 + r, c);
    __syncwarp();
}

__global__ void __launch_bounds__(THREADS, 2)
pointnet_sa_hmma5_kernel(
    const float* __restrict__ xyz, const float* __restrict__ pts,
    const float* __restrict__ xyzs, const int* __restrict__ nbr,
    const float* __restrict__ vmask,
    const float* __restrict__ w0, const float* __restrict__ b0,
    const float* __restrict__ g0, const float* __restrict__ be0,
    const float* __restrict__ m0, const float* __restrict__ v0,
    const float* __restrict__ w1, const float* __restrict__ b1,
    const float* __restrict__ g1, const float* __restrict__ be1,
    const float* __restrict__ m1, const float* __restrict__ v1,
    const float* __restrict__ w2, const float* __restrict__ b2,
    const float* __restrict__ g2, const float* __restrict__ be2,
    const float* __restrict__ m2, const float* __restrict__ v2,
    float* __restrict__ out, int copies)
{
    extern __shared__ u32 smu[];
    float* smf = (float*)smu;
    const int tid = threadIdx.x;

    // ================= one-time setup =================
    if (tid < 64) {
        float s = g0[tid] * rsqrtf(v0[tid] + 1e-5f);
        smf[OFF_S0 + tid] = s;
        smf[OFF_T0 + tid] = (b0[tid] - m0[tid]) * s + be0[tid];
        float s1 = g1[tid] * rsqrtf(v1[tid] + 1e-5f);
        smf[OFF_S1 + tid] = s1;
        smf[OFF_T1 + tid] = (b1[tid] - m1[tid]) * s1 + be1[tid];
    }
    if (tid < 128) {
        float s = g2[tid] * rsqrtf(v2[tid] + 1e-5f);
        smf[OFF_S2 + tid] = s;
        smf[OFF_T2 + tid] = (b2[tid] - m2[tid]) * s + be2[tid];
    }
    __syncthreads();
    for (int i = tid; i < 64 * 40; i += THREADS) {
        int n = i / 40, pos = i % 40;
        int q = pos & 7;
        int p = (pos & ~7) + ((q & 1) ? (q >> 1) + 4 : (q >> 1));
        int k0 = 2 * p, k1 = k0 + 1;
        float s = smf[OFF_S0 + n];
        float a = 0.f, b = 0.f;
        if (k0 < 67) { int sr = (k0 < 64) ? k0 + 3 : k0 - 64; a = w0[sr * 64 + n] * s; }
        if (k1 < 67) { int sr = (k1 < 64) ? k1 + 3 : k1 - 64; b = w0[sr * 64 + n] * s; }
        smu[OFF_W0 + i] = packh2(a, b);
    }
    for (int i = tid; i < 64 * 40; i += THREADS) {
        int n = i / 40, pos = i % 40;
        int q = pos & 7;
        int p = (pos & ~7) + ((q & 1) ? (q >> 1) + 4 : (q >> 1));
        int k0 = 2 * p;
        float s = smf[OFF_S1 + n];
        float a = (k0 < 64)     ? w1[k0 * 64 + n] * s       : 0.f;
        float b = (k0 + 1 < 64) ? w1[(k0 + 1) * 64 + n] * s : 0.f;
        smu[OFF_W1 + i] = packh2(a, b);
    }
    for (int i = tid; i < 128 * 40; i += THREADS) {
        int n = i / 40, pos = i % 40;
        int q = pos & 7;
        int p = (pos & ~7) + ((q & 1) ? (q >> 1) + 4 : (q >> 1));
        int k0 = 2 * p;
        float s = smf[OFF_S2 + n];
        float a = (k0 < 64)     ? w2[k0 * 128 + n] * s       : 0.f;
        float b = (k0 + 1 < 64) ? w2[(k0 + 1) * 128 + n] * s : 0.f;
        smu[OFF_W2 + i] = packh2(a, b);
    }
    __syncthreads();

    const int lane = tid & 31;
    const int warp = tid >> 5;
    const int r = lane >> 2;       // groupID in quad layout
    const int c = lane & 3;        // threadID in group
    const int base = warp * 32;    // this warp's private 32-row act block

    u64* AHu = (u64*)(smu + OFF_AH);
    const u64* W0u = (const u64*)(smu + OFF_W0);
    const u64* W1u = (const u64*)(smu + OFF_W1);
    const u64* W2u = (const u64*)(smu + OFF_W2);
    float* stage = smf + OFF_STAGE + warp * 256;

    // ================= persistent warp-task loop =================
    for (int task = blockIdx.x * WARPS + warp; task < NTASK; task += GRID * WARPS) {

        // ---- gather: lane owns local row base+lane = global row task*32+lane ----
        {
            const int grp = task * 2 + (lane >> 4);
            const int b = grp >> 14, n = grp & (NS_SZ - 1);
            const int e = grp * 16 + (lane & 15);
            const int idx = nbr[e];
            const float mk = vmask[e];
            const float4* pp = (const float4*)(pts + (size_t)(b * HW_SZ + idx) * 64);
            u32* AH = smu + OFF_AH + (base + lane) * 40;
            #pragma unroll
            for (int i = 0; i < 16; i++) {
                float4 v = pp[i];
                AH[POS(2 * i)]     = packh2(v.x * mk, v.y * mk);
                AH[POS(2 * i + 1)] = packh2(v.z * mk, v.w * mk);
            }
            const float* cp = xyzs + (size_t)(b * NS_SZ + n) * 3;
            const float* gx = xyz + (size_t)(b * HW_SZ + idx) * 3;
            AH[32] = packh2(gx[0] * mk - cp[0], gx[1] * mk - cp[1]);   // POS(32)=32
            AH[34] = packh2(gx[2] * mk - cp[2], 0.f);                  // POS(33)=34
            AH[33] = 0;
            #pragma unroll
            for (int z = 35; z < 40; z++) AH[z] = 0;
        }
        __syncwarp();

        // ===== layers 0 and 1 =====
        layer_n64<5>(AHu, W0u, smf + OFF_T0, base, r, c);
        layer_n64<4>(AHu, W1u, smf + OFF_T1, base, r, c);

        // ===== layer 2: K=64, N=128 two passes; maxpool per 16-row group =====
        #pragma unroll 1
        for (int p = 0; p < 2; p++) {
            float d[2][8][4];
            #pragma unroll
            for (int m = 0; m < 2; m++)
                #pragma unroll
                for (int j = 0; j < 8; j++)
                    { d[m][j][0]=0.f; d[m][j][1]=0.f; d[m][j][2]=0.f; d[m][j][3]=0.f; }
            #pragma unroll
            for (int kt = 0; kt < 4; kt++) {
                u32 a0[4], a1[4];
                load_afrag(a0, AHu, base + r,      kt, c);
                load_afrag(a1, AHu, base + 16 + r, kt, c);
                #pragma unroll
                for (int j = 0; j < 8; j++) {
                    u64 b = W2u[(64 * p + 8 * j + r) * 20 + kt * 4 + c];
                    u32 b0 = lo32(b), b1 = hi32(b);
                    mma_f16(d[0][j], a0[0], a0[1], a0[2], a0[3], b0, b1);
                    mma_f16(d[1][j], a1[0], a1[1], a1[2], a1[3], b0, b1);
                }
            }
            #pragma unroll
            for (int m = 0; m < 2; m++) {
                float mx0[8], mx1[8];
                #pragma unroll
                for (int j = 0; j < 8; j++) {
                    mx0[j] = fmaxf(d[m][j][0], d[m][j][2]);
                    mx1[j] = fmaxf(d[m][j][1], d[m][j][3]);
                }
                #pragma unroll
                for (int off = 4; off <= 16; off <<= 1) {
                    #pragma unroll
                    for (int j = 0; j < 8; j++) {
                        mx0[j] = fmaxf(mx0[j], __shfl_xor_sync(0xffffffffu, mx0[j], off));
                        mx1[j] = fmaxf(mx1[j], __shfl_xor_sync(0xffffffffu, mx1[j], off));
                    }
                }
                if (lane < 4) {
                    #pragma unroll
                    for (int j = 0; j < 8; j++) {
                        float2 tv = *(const float2*)(smf + OFF_T2 + 64 * p + 8 * j + 2 * c);
                        float2 o;
                        o.x = fmaxf(mx0[j] + tv.x, 0.f);
                        o.y = fmaxf(mx1[j] + tv.y, 0.f);
                        *(float2*)(stage + m * 128 + 64 * p + 8 * j + 2 * c) = o;
                    }
                }
            }
        }
        __syncwarp();

        // ---- coalesced output: 2 groups x 128 floats ----
        #pragma unroll
        for (int m = 0; m < 2; m++) {
            float4 o = ((const float4*)(stage + m * 128))[lane];
            const long ofs = (long)(task * 2 + m) * 128 + 4 * lane;
            *(float4*)(out + ofs) = o;
            if (copies > 1) *(float4*)(out + OUT_ONE + ofs) = o;
        }
        __syncwarp();
    }
}

extern "C" void kernel_launch(void* const* d_in, const int* in_sizes, int n_in,
                              void* d_out, int out_size)
{
    const float* xyz   = (const float*)d_in[0];
    const float* pts   = (const float*)d_in[1];
    const float* xyzs  = (const float*)d_in[2];
    const int*   nbr   = (const int*)  d_in[3];
    const float* vmask = (const float*)d_in[4];
    const float* w0  = (const float*)d_in[5];
    const float* b0  = (const float*)d_in[6];
    const float* g0  = (const float*)d_in[7];
    const float* be0 = (const float*)d_in[8];
    const float* m0  = (const float*)d_in[9];
    const float* v0  = (const float*)d_in[10];
    const float* w1  = (const float*)d_in[11];
    const float* b1  = (const float*)d_in[12];
    const float* g1  = (const float*)d_in[13];
    const float* be1 = (const float*)d_in[14];
    const float* m1  = (const float*)d_in[15];
    const float* v1  = (const float*)d_in[16];
    const float* w2  = (const float*)d_in[17];
    const float* b2  = (const float*)d_in[18];
    const float* g2  = (const float*)d_in[19];
    const float* be2 = (const float*)d_in[20];
    const float* m2  = (const float*)d_in[21];
    const float* v2  = (const float*)d_in[22];

    int copies = (out_size >= 2 * OUT_ONE) ? 2 : 1;

    cudaFuncSetAttribute(pointnet_sa_hmma5_kernel,
                         cudaFuncAttributeMaxDynamicSharedMemorySize, SMEM_BYTES);

    pointnet_sa_hmma5_kernel<<<GRID, THREADS, SMEM_BYTES>>>(
        xyz, pts, xyzs, nbr, vmask,
        w0, b0, g0, be0, m0, v0,
        w1, b1, g1, be1, m1, v1,
        w2, b2, g2, be2, m2, v2,
        (float*)d_out, copies);
}

// round 15
// speedup vs baseline: 3.3269x; 1.1153x over previous
#include <cuda_runtime.h>
#include <cuda_fp16.h>
#include <cstdint>

// PointNetSaModule via mma.sync fp16 (sm_103-safe HMMA), persistent warps.
// R14: register-chained layers. D-fragment of layer L == A-fragment of layer
// L+1 for the same thread (m16n8k16 maps line up), so acts never return to
// smem after the gather. Bias+ReLU applied in registers between layers.

typedef uint32_t u32;
typedef uint64_t u64;

#define NS_SZ  16384
#define HW_SZ  65536
#define OUT_ONE (4 * 16384 * 128)
#define THREADS 256
#define WARPS   8
#define NTASK   32768          // 1M rows / 32
#define GRID    304            // 2 per SM

// u32 offsets in dynamic smem
#define OFF_T0    0
#define OFF_T1    64
#define OFF_T2    128
#define OFF_S0    256
#define OFF_S1    320
#define OFF_S2    384
#define OFF_AH    512                     // 256 rows x 40 u32 (fp16x2 kpairs)
#define OFF_W0    (OFF_AH + 256 * 40)     // (64 x 40)
#define OFF_W1    (OFF_W0 + 64 * 40)
#define OFF_W2    (OFF_W1 + 64 * 40)      // (128 x 40)
#define OFF_STAGE (OFF_W2 + 128 * 40)     // 8 warps x 256 f32
#define SMEM_U32  (OFF_STAGE + WARPS * 256)
#define SMEM_BYTES (SMEM_U32 * 4)         // 92160

// physical slot of logical kpair p (interleave (c, c+4) adjacent within ktile)
__device__ __forceinline__ int POS(int p) {
    int q = p & 7;
    return (p & ~7) + ((q < 4) ? 2 * q : 2 * (q - 4) + 1);
}

__device__ __forceinline__ u32 packh2(float lo, float hi) {   // low half = lo
    __half2 h = __floats2half2_rn(lo, hi);
    return *(u32*)&h;
}
__device__ __forceinline__ void mma_f16(float* d, u32 a0, u32 a1, u32 a2, u32 a3,
                                        u32 b0, u32 b1) {
    asm("mma.sync.aligned.m16n8k16.row.col.f32.f16.f16.f32 "
        "{%0,%1,%2,%3}, {%4,%5,%6,%7}, {%8,%9}, {%0,%1,%2,%3};"
        : "+f"(d[0]), "+f"(d[1]), "+f"(d[2]), "+f"(d[3])
        : "r"(a0), "r"(a1), "r"(a2), "r"(a3), "r"(b0), "r"(b1));
}
__device__ __forceinline__ u32 lo32(u64 v) { return (u32)v; }
__device__ __forceinline__ u32 hi32(u64 v) { return (u32)(v >> 32); }

// D fragments (one m-tile, 8 n-tiles) + bias/ReLU -> A fragments for next layer.
// afr[kt] = {a0,a1,a2,a3} per PTX m16n8k16 A map; pure thread-local repack.
__device__ __forceinline__ void d2afrag(const float d[8][4], const float* T, int c,
                                        u32 afr[4][4])
{
    #pragma unroll
    for (int kt = 0; kt < 4; kt++) {
        float2 tA = *(const float2*)(T + 16 * kt + 2 * c);
        float2 tB = *(const float2*)(T + 16 * kt + 8 + 2 * c);
        afr[kt][0] = packh2(fmaxf(d[2*kt][0]   + tA.x, 0.f), fmaxf(d[2*kt][1]   + tA.y, 0.f));
        afr[kt][1] = packh2(fmaxf(d[2*kt][2]   + tA.x, 0.f), fmaxf(d[2*kt][3]   + tA.y, 0.f));
        afr[kt][2] = packh2(fmaxf(d[2*kt+1][0] + tB.x, 0.f), fmaxf(d[2*kt+1][1] + tB.y, 0.f));
        afr[kt][3] = packh2(fmaxf(d[2*kt+1][2] + tB.x, 0.f), fmaxf(d[2*kt+1][3] + tB.y, 0.f));
    }
}

// One N=64 layer from register A-frags (4 ktiles); writes fresh d[2][8][4].
__device__ __forceinline__ void layer_reg(const u32 afr[2][4][4], const u64* Wu,
        float d[2][8][4], int r, int c, int coloff)
{
    #pragma unroll
    for (int m = 0; m < 2; m++)
        #pragma unroll
        for (int j = 0; j < 8; j++)
            { d[m][j][0]=0.f; d[m][j][1]=0.f; d[m][j][2]=0.f; d[m][j][3]=0.f; }
    #pragma unroll
    for (int kt = 0; kt < 4; kt++) {
        #pragma unroll
        for (int j = 0; j < 8; j++) {
            u64 b = Wu[(coloff + 8 * j + r) * 20 + kt * 4 + c];
            u32 b0 = lo32(b), b1 = hi32(b);
            mma_f16(d[0][j], afr[0][kt][0], afr[0][kt][1], afr[0][kt][2], afr[0][kt][3], b0, b1);
            mma_f16(d[1][j], afr[1][kt][0], afr[1][kt][1], afr[1][kt][2], afr[1][kt][3], b0, b1);
        }
    }
}

__global__ void __launch_bounds__(THREADS, 2)
pointnet_sa_hmma6_kernel(
    const float* __restrict__ xyz, const float* __restrict__ pts,
    const float* __restrict__ xyzs, const int* __restrict__ nbr,
    const float* __restrict__ vmask,
    const float* __restrict__ w0, const float* __restrict__ b0,
    const float* __restrict__ g0, const float* __restrict__ be0,
    const float* __restrict__ m0, const float* __restrict__ v0,
    const float* __restrict__ w1, const float* __restrict__ b1,
    const float* __restrict__ g1, const float* __restrict__ be1,
    const float* __restrict__ m1, const float* __restrict__ v1,
    const float* __restrict__ w2, const float* __restrict__ b2,
    const float* __restrict__ g2, const float* __restrict__ be2,
    const float* __restrict__ m2, const float* __restrict__ v2,
    float* __restrict__ out, int copies)
{
    extern __shared__ u32 smu[];
    float* smf = (float*)smu;
    const int tid = threadIdx.x;

    // ================= one-time setup =================
    if (tid < 64) {
        float s = g0[tid] * rsqrtf(v0[tid] + 1e-5f);
        smf[OFF_S0 + tid] = s;
        smf[OFF_T0 + tid] = (b0[tid] - m0[tid]) * s + be0[tid];
        float s1 = g1[tid] * rsqrtf(v1[tid] + 1e-5f);
        smf[OFF_S1 + tid] = s1;
        smf[OFF_T1 + tid] = (b1[tid] - m1[tid]) * s1 + be1[tid];
    }
    if (tid < 128) {
        float s = g2[tid] * rsqrtf(v2[tid] + 1e-5f);
        smf[OFF_S2 + tid] = s;
        smf[OFF_T2 + tid] = (b2[tid] - m2[tid]) * s + be2[tid];
    }
    __syncthreads();
    for (int i = tid; i < 64 * 40; i += THREADS) {
        int n = i / 40, pos = i % 40;
        int q = pos & 7;
        int p = (pos & ~7) + ((q & 1) ? (q >> 1) + 4 : (q >> 1));
        int k0 = 2 * p, k1 = k0 + 1;
        float s = smf[OFF_S0 + n];
        float a = 0.f, b = 0.f;
        if (k0 < 67) { int sr = (k0 < 64) ? k0 + 3 : k0 - 64; a = w0[sr * 64 + n] * s; }
        if (k1 < 67) { int sr = (k1 < 64) ? k1 + 3 : k1 - 64; b = w0[sr * 64 + n] * s; }
        smu[OFF_W0 + i] = packh2(a, b);
    }
    for (int i = tid; i < 64 * 40; i += THREADS) {
        int n = i / 40, pos = i % 40;
        int q = pos & 7;
        int p = (pos & ~7) + ((q & 1) ? (q >> 1) + 4 : (q >> 1));
        int k0 = 2 * p;
        float s = smf[OFF_S1 + n];
        float a = (k0 < 64)     ? w1[k0 * 64 + n] * s       : 0.f;
        float b = (k0 + 1 < 64) ? w1[(k0 + 1) * 64 + n] * s : 0.f;
        smu[OFF_W1 + i] = packh2(a, b);
    }
    for (int i = tid; i < 128 * 40; i += THREADS) {
        int n = i / 40, pos = i % 40;
        int q = pos & 7;
        int p = (pos & ~7) + ((q & 1) ? (q >> 1) + 4 : (q >> 1));
        int k0 = 2 * p;
        float s = smf[OFF_S2 + n];
        float a = (k0 < 64)     ? w2[k0 * 128 + n] * s       : 0.f;
        float b = (k0 + 1 < 64) ? w2[(k0 + 1) * 128 + n] * s : 0.f;
        smu[OFF_W2 + i] = packh2(a, b);
    }
    __syncthreads();

    const int lane = tid & 31;
    const int warp = tid >> 5;
    const int r = lane >> 2;       // groupID in quad layout
    const int c = lane & 3;        // threadID in group
    const int base = warp * 32;    // this warp's private 32-row act block

    const u64* AHu = (const u64*)(smu + OFF_AH);
    const u64* W0u = (const u64*)(smu + OFF_W0);
    const u64* W1u = (const u64*)(smu + OFF_W1);
    const u64* W2u = (const u64*)(smu + OFF_W2);
    float* stage = smf + OFF_STAGE + warp * 256;

    // ================= persistent warp-task loop =================
    for (int task = blockIdx.x * WARPS + warp; task < NTASK; task += GRID * WARPS) {

        // ---- gather: lane owns local row base+lane = global row task*32+lane ----
        {
            const int grp = task * 2 + (lane >> 4);
            const int b = grp >> 14, n = grp & (NS_SZ - 1);
            const int e = grp * 16 + (lane & 15);
            const int idx = nbr[e];
            const float mk = vmask[e];
            const float4* pp = (const float4*)(pts + (size_t)(b * HW_SZ + idx) * 64);
            u32* AH = smu + OFF_AH + (base + lane) * 40;
            #pragma unroll
            for (int i = 0; i < 16; i++) {
                float4 v = pp[i];
                AH[POS(2 * i)]     = packh2(v.x * mk, v.y * mk);
                AH[POS(2 * i + 1)] = packh2(v.z * mk, v.w * mk);
            }
            const float* cp = xyzs + (size_t)(b * NS_SZ + n) * 3;
            const float* gx = xyz + (size_t)(b * HW_SZ + idx) * 3;
            AH[32] = packh2(gx[0] * mk - cp[0], gx[1] * mk - cp[1]);   // POS(32)=32
            AH[34] = packh2(gx[2] * mk - cp[2], 0.f);                  // POS(33)=34
            AH[33] = 0;
            #pragma unroll
            for (int z = 35; z < 40; z++) AH[z] = 0;
        }
        __syncwarp();

        // ===== layer 0: A from smem (5 ktiles), d0 in regs =====
        float d[2][8][4];
        #pragma unroll
        for (int m = 0; m < 2; m++)
            #pragma unroll
            for (int j = 0; j < 8; j++)
                { d[m][j][0]=0.f; d[m][j][1]=0.f; d[m][j][2]=0.f; d[m][j][3]=0.f; }
        #pragma unroll
        for (int kt = 0; kt < 5; kt++) {
            u32 a0[4], a1[4];
            {
                u64 v0 = AHu[(base + r) * 20 + kt * 4 + c];
                u64 v1 = AHu[(base + r + 8) * 20 + kt * 4 + c];
                a0[0] = lo32(v0); a0[2] = hi32(v0);
                a0[1] = lo32(v1); a0[3] = hi32(v1);
                u64 w0v = AHu[(base + 16 + r) * 20 + kt * 4 + c];
                u64 w1v = AHu[(base + 24 + r) * 20 + kt * 4 + c];
                a1[0] = lo32(w0v); a1[2] = hi32(w0v);
                a1[1] = lo32(w1v); a1[3] = hi32(w1v);
            }
            #pragma unroll
            for (int j = 0; j < 8; j++) {
                u64 b = W0u[(8 * j + r) * 20 + kt * 4 + c];
                u32 b0 = lo32(b), b1 = hi32(b);
                mma_f16(d[0][j], a0[0], a0[1], a0[2], a0[3], b0, b1);
                mma_f16(d[1][j], a1[0], a1[1], a1[2], a1[3], b0, b1);
            }
        }
        __syncwarp();   // AH reads done; safe for next task's gather

        // ---- register repack: d0 + bias/ReLU -> A frags for layer 1 ----
        u32 afr[2][4][4];
        d2afrag(d[0], smf + OFF_T0, c, afr[0]);
        d2afrag(d[1], smf + OFF_T0, c, afr[1]);

        // ===== layer 1 (register A) =====
        layer_reg(afr, W1u, d, r, c, 0);
        d2afrag(d[0], smf + OFF_T1, c, afr[0]);
        d2afrag(d[1], smf + OFF_T1, c, afr[1]);

        // ===== layer 2: two N=64 passes; maxpool per 16-row group =====
        #pragma unroll 1
        for (int p = 0; p < 2; p++) {
            layer_reg(afr, W2u, d, r, c, 64 * p);
            #pragma unroll
            for (int m = 0; m < 2; m++) {
                float mx0[8], mx1[8];
                #pragma unroll
                for (int j = 0; j < 8; j++) {
                    mx0[j] = fmaxf(d[m][j][0], d[m][j][2]);
                    mx1[j] = fmaxf(d[m][j][1], d[m][j][3]);
                }
                #pragma unroll
                for (int off = 4; off <= 16; off <<= 1) {
                    #pragma unroll
                    for (int j = 0; j < 8; j++) {
                        mx0[j] = fmaxf(mx0[j], __shfl_xor_sync(0xffffffffu, mx0[j], off));
                        mx1[j] = fmaxf(mx1[j], __shfl_xor_sync(0xffffffffu, mx1[j], off));
                    }
                }
                if (lane < 4) {
                    #pragma unroll
                    for (int j = 0; j < 8; j++) {
                        float2 tv = *(const float2*)(smf + OFF_T2 + 64 * p + 8 * j + 2 * c);
                        float2 o;
                        o.x = fmaxf(mx0[j] + tv.x, 0.f);
                        o.y = fmaxf(mx1[j] + tv.y, 0.f);
                        *(float2*)(stage + m * 128 + 64 * p + 8 * j + 2 * c) = o;
                    }
                }
            }
        }
        __syncwarp();

        // ---- coalesced output: 2 groups x 128 floats ----
        #pragma unroll
        for (int m = 0; m < 2; m++) {
            float4 o = ((const float4*)(stage + m * 128))[lane];
            const long ofs = (long)(task * 2 + m) * 128 + 4 * lane;
            *(float4*)(out + ofs) = o;
            if (copies > 1) *(float4*)(out + OUT_ONE + ofs) = o;
        }
        __syncwarp();
    }
}

extern "C" void kernel_launch(void* const* d_in, const int* in_sizes, int n_in,
                              void* d_out, int out_size)
{
    const float* xyz   = (const float*)d_in[0];
    const float* pts   = (const float*)d_in[1];
    const float* xyzs  = (const float*)d_in[2];
    const int*   nbr   = (const int*)  d_in[3];
    const float* vmask = (const float*)d_in[4];
    const float* w0  = (const float*)d_in[5];
    const float* b0  = (const float*)d_in[6];
    const float* g0  = (const float*)d_in[7];
    const float* be0 = (const float*)d_in[8];
    const float* m0  = (const float*)d_in[9];
    const float* v0  = (const float*)d_in[10];
    const float* w1  = (const float*)d_in[11];
    const float* b1  = (const float*)d_in[12];
    const float* g1  = (const float*)d_in[13];
    const float* be1 = (const float*)d_in[14];
    const float* m1  = (const float*)d_in[15];
    const float* v1  = (const float*)d_in[16];
    const float* w2  = (const float*)d_in[17];
    const float* b2  = (const float*)d_in[18];
    const float* g2  = (const float*)d_in[19];
    const float* be2 = (const float*)d_in[20];
    const float* m2  = (const float*)d_in[21];
    const float* v2  = (const float*)d_in[22];

    int copies = (out_size >= 2 * OUT_ONE) ? 2 : 1;

    cudaFuncSetAttribute(pointnet_sa_hmma6_kernel,
                         cudaFuncAttributeMaxDynamicSharedMemorySize, SMEM_BYTES);

    pointnet_sa_hmma6_kernel<<<GRID, THREADS, SMEM_BYTES>>>(
        xyz, pts, xyzs, nbr, vmask,
        w0, b0, g0, be0, m0, v0,
        w1, b1, g1, be1, m1, v1,
        w2, b2, g2, be2, m2, v2,
        (float*)d_out, copies);
}